// round 9
// baseline (speedup 1.0000x reference)
#include <cuda_runtime.h>
#include <cuda_bf16.h>
#include <cstdint>

#define NN 64
#define CC 32
#define MM 4000
#define LL 2000
#define DD 16
#define OO 32

// ---------------------------------------------------------------------------
// Global scratch
// xTb[m][row][c]: row = 2n + part (part 0 = hi bf16, 1 = lo bf16), c in [0,32)
// ---------------------------------------------------------------------------
__device__ __align__(256) __nv_bfloat16 g_xTb[(size_t)MM * 128 * 32];   // 32.8 MB
__device__ __align__(256) float g_out_ln[(size_t)LL * 64 * 32];         // 16.4 MB

// SMEM map: chunk = k 64 (2 d-slices).  A: 128 rows x 128B, B: 64 rows x 128B.
// Row stride 144 B (9 x 16B granules, odd -> conflict-free ldmatrix/LDS).
#define RSTRIDE 144
#define A_BUF (128 * RSTRIDE)           // 18432
#define B_BUF (64 * RSTRIDE)            // 9216
#define OFF_A0 0u
#define OFF_A1 18432u
#define OFF_B0 36864u
#define OFF_B1 46080u
#define SMEM_SZ 55296

__device__ __forceinline__ uint32_t smem_u32_of(const void* p) {
    uint32_t a;
    asm("{ .reg .u64 t; cvta.to.shared.u64 t, %1; cvt.u32.u64 %0, t; }"
        : "=r"(a) : "l"(p));
    return a;
}

// bf16 hi/lo split of a pair (v0 -> low half, v1 -> high half)
__device__ __forceinline__ void split_pair(float v0, float v1,
                                           uint32_t& h2, uint32_t& l2) {
    asm("cvt.rn.bf16x2.f32 %0, %1, %2;" : "=r"(h2) : "f"(v1), "f"(v0));
    float h0 = __uint_as_float(h2 << 16);
    float h1 = __uint_as_float(h2 & 0xffff0000u);
    float r0 = v0 - h0, r1 = v1 - h1;
    asm("cvt.rn.bf16x2.f32 %0, %1, %2;" : "=r"(l2) : "f"(r1), "f"(r0));
}

// ---------------------------------------------------------------------------
// Kernel 1: x[n][c][m] -> g_xTb[m][2n|2n+1][c]  (hi/lo bf16)
// ---------------------------------------------------------------------------
__global__ void build_xTb_kernel(const float* __restrict__ x) {
    __shared__ float tile[32 * 33];
    int m0 = blockIdx.x * 32;
    int n  = blockIdx.y;
    int tid = threadIdx.x;
#pragma unroll
    for (int it = 0; it < 4; it++) {
        int t = tid + 256 * it;
        int c = t >> 5, mi = t & 31;
        tile[c * 33 + mi] = x[((size_t)n * CC + c) * MM + m0 + mi];
    }
    __syncthreads();
    int mi = tid >> 3, c4 = tid & 7;
    float v0 = tile[(c4 * 4 + 0) * 33 + mi];
    float v1 = tile[(c4 * 4 + 1) * 33 + mi];
    float v2 = tile[(c4 * 4 + 2) * 33 + mi];
    float v3 = tile[(c4 * 4 + 3) * 33 + mi];
    uint32_t h2a, l2a, h2b, l2b;
    split_pair(v0, v1, h2a, l2a);
    split_pair(v2, v3, h2b, l2b);
    char* base = (char*)g_xTb + ((size_t)(m0 + mi) * 128 + 2 * n) * 64 + c4 * 8;
    *(uint2*)base        = make_uint2(h2a, h2b);
    *(uint2*)(base + 64) = make_uint2(l2a, l2b);
}

// ---------------------------------------------------------------------------
// Kernel 2: per-l gather-GEMM on legacy tensor cores (mma.sync bf16)
// chunk = 2 d-slices (k=64); 8 chunks; 4 CTAs/SM.
// ---------------------------------------------------------------------------
struct B4 { float2 a[4], b[4]; };

__device__ __forceinline__ void stage_A(uint32_t dstb, const int* __restrict__ idx,
                                        int l, int ch, int tid) {
#pragma unroll
    for (int tt = 0; tt < 8; tt++) {
        int u  = tid + 128 * tt;                    // u < 1024
        int dd = u >> 9;                            // 0..1
        int r  = (u >> 2) & 127;
        int g  = u & 3;
        int m  = __ldg(idx + l * DD + ch * 2 + dd);
        const char* src = (const char*)g_xTb + ((size_t)m * 128 + r) * 64 + g * 16;
        uint32_t dst = dstb + (uint32_t)(r * RSTRIDE + dd * 64 + g * 16);
        asm volatile("cp.async.cg.shared.global [%0], [%1], 16;"
                     :: "r"(dst), "l"(src));
    }
    asm volatile("cp.async.commit_group;" ::: "memory");
}

__device__ __forceinline__ void ldg_B(B4& r, const float* __restrict__ W,
                                      int l, int ch, int tid) {
#pragma unroll
    for (int t = 0; t < 4; t++) {
        int q = tid + 128 * t;                      // q < 512
        int o = q >> 4, cp = q & 15;
        const float2* p = (const float2*)(W + ((size_t)l * 1024 + o * 32 + 2 * cp) * 16
                                          + ch * 2);
        r.a[t] = p[0];          // c = 2cp,   d = 2ch, 2ch+1
        r.b[t] = p[8];          // c = 2cp+1  (16 floats = 8 float2 further)
    }
}

__device__ __forceinline__ void sts_B(char* bb, const B4& r, int tid) {
#pragma unroll
    for (int t = 0; t < 4; t++) {
        int q = tid + 128 * t;
        int o = q >> 4, cp = q & 15;
        const float* va = (const float*)&r.a[t];
        const float* vb = (const float*)&r.b[t];
#pragma unroll
        for (int dd = 0; dd < 2; dd++) {
            uint32_t h2, l2;
            split_pair(va[dd], vb[dd], h2, l2);
            char* p = bb + o * RSTRIDE + dd * 64 + cp * 4;
            *(uint32_t*)p                    = h2;   // rows 0..31  = W_hi
            *(uint32_t*)(p + 32 * RSTRIDE)   = l2;   // rows 32..63 = W_lo
        }
    }
}

#define LDMX4(r, addr) \
    asm volatile("ldmatrix.sync.aligned.m8n8.x4.shared.b16 {%0,%1,%2,%3}, [%4];" \
                 : "=r"((r)[0]), "=r"((r)[1]), "=r"((r)[2]), "=r"((r)[3]) \
                 : "r"(addr))

#define LDS32(r, addr) \
    asm volatile("ld.shared.b32 %0, [%1];" : "=r"(r) : "r"(addr))

#define MMA16816(d, a, b) \
    asm volatile("mma.sync.aligned.m16n8k16.row.col.f32.bf16.bf16.f32 " \
                 "{%0,%1,%2,%3}, {%4,%5,%6,%7}, {%8,%9}, {%0,%1,%2,%3};" \
                 : "+f"((d)[0]), "+f"((d)[1]), "+f"((d)[2]), "+f"((d)[3]) \
                 : "r"((a)[0]), "r"((a)[1]), "r"((a)[2]), "r"((a)[3]), \
                   "r"((b)[0]), "r"((b)[1]))

__device__ __forceinline__ void compute_chunk(uint32_t As, uint32_t Bs,
                                              int wid, int lane,
                                              float acc[2][8][4]) {
    const uint32_t a_row = (lane & 7) + ((lane >> 3) & 1) * 8;
    const uint32_t a0b = As + (32 * wid + a_row) * RSTRIDE + (lane >> 4) * 16;
    const uint32_t a1b = a0b + 16 * RSTRIDE;
    const uint32_t bbs = Bs + (lane >> 2) * RSTRIDE + (lane & 3) * 4;
#pragma unroll
    for (int ks = 0; ks < 4; ks++) {
        uint32_t a0[4], a1[4];
        LDMX4(a0, a0b + ks * 32);
        LDMX4(a1, a1b + ks * 32);
        uint32_t bb[8][2];
#pragma unroll
        for (int nt = 0; nt < 8; nt++) {
            uint32_t ba = bbs + nt * (8 * RSTRIDE) + ks * 32;
            LDS32(bb[nt][0], ba);
            LDS32(bb[nt][1], ba + 16);
        }
#pragma unroll
        for (int nt = 0; nt < 8; nt++) {
            MMA16816(acc[0][nt], a0, bb[nt]);
            MMA16816(acc[1][nt], a1, bb[nt]);
        }
    }
}

__global__ __launch_bounds__(128, 4)
void gemm_kernel(const float* __restrict__ W, const int* __restrict__ idx) {
    extern __shared__ char sm[];
    const uint32_t sb = smem_u32_of(sm);
    const int tid = threadIdx.x, wid = tid >> 5, lane = tid & 31;

    B4 br;
    for (int l = blockIdx.x; l < LL; l += gridDim.x) {
        float acc[2][8][4];
#pragma unroll
        for (int t = 0; t < 2; t++)
#pragma unroll
            for (int nt = 0; nt < 8; nt++)
#pragma unroll
                for (int r = 0; r < 4; r++) acc[t][nt][r] = 0.0f;

        // prologue: chunk 0
        stage_A(sb + OFF_A0, idx, l, 0, tid);
        ldg_B(br, W, l, 0, tid);
        asm volatile("cp.async.wait_group 0;" ::: "memory");
        sts_B(sm + OFF_B0, br, tid);
        __syncthreads();

#pragma unroll
        for (int ch = 0; ch < 8; ch++) {
            const int s = ch & 1;
            if (ch < 7) {
                stage_A(sb + (s ? OFF_A0 : OFF_A1), idx, l, ch + 1, tid);
                ldg_B(br, W, l, ch + 1, tid);
            }
            compute_chunk(sb + (s ? OFF_A1 : OFF_A0),
                          sb + (s ? OFF_B1 : OFF_B0), wid, lane, acc);
            if (ch < 7) {
                asm volatile("cp.async.wait_group 0;" ::: "memory");
                sts_B(sm + (s ? OFF_B0 : OFF_B1), br, tid);
                __syncthreads();
            }
        }

        // epilogue: fold q (cols o vs o+32), fold hi/lo row pairs, store
#pragma unroll
        for (int t = 0; t < 2; t++)
#pragma unroll
            for (int nt = 0; nt < 4; nt++)
#pragma unroll
                for (int r = 0; r < 4; r++)
                    acc[t][nt][r] += acc[t][nt + 4][r];

        float v[2][4][4];
#pragma unroll
        for (int t = 0; t < 2; t++)
#pragma unroll
            for (int nt = 0; nt < 4; nt++)
#pragma unroll
                for (int r = 0; r < 4; r++)
                    v[t][nt][r] = acc[t][nt][r]
                        + __shfl_xor_sync(0xffffffffu, acc[t][nt][r], 4);

        if ((lane & 4) == 0) {
            const int ghalf = lane >> 3;            // g/2 for even g
            const int tig2  = (lane & 3) * 2;
#pragma unroll
            for (int t = 0; t < 2; t++)
#pragma unroll
                for (int u = 0; u < 2; u++) {
                    int n = wid * 16 + 8 * t + 4 * u + ghalf;
                    float* op = g_out_ln + ((size_t)l * 64 + n) * 32;
#pragma unroll
                    for (int nt = 0; nt < 4; nt++) {
                        int o = nt * 8 + tig2;
                        *(float2*)(op + o) = make_float2(v[t][nt][2 * u],
                                                         v[t][nt][2 * u + 1]);
                    }
                }
        }
        __syncthreads();
    }
}

// ---------------------------------------------------------------------------
// Kernel 3: g_out_ln[l][p] + bias -> out[p][l]   (p = n*32 + o, o = p & 31)
// ---------------------------------------------------------------------------
__global__ void out_transpose_kernel(const float* __restrict__ bias,
                                     float* __restrict__ out) {
    __shared__ float t[32][33];
    int p0 = blockIdx.x * 32, l0 = blockIdx.y * 32;
    int tx = threadIdx.x, ty = threadIdx.y;
#pragma unroll
    for (int j = 0; j < 32; j += 8) {
        int l = l0 + ty + j;
        if (l < LL)
            t[ty + j][tx] = g_out_ln[(size_t)l * 2048 + p0 + tx]
                          + __ldg(bias + l * OO + (tx & 31));
    }
    __syncthreads();
#pragma unroll
    for (int j = 0; j < 32; j += 8) {
        int l = l0 + tx, p = p0 + ty + j;
        if (l < LL) out[(size_t)p * LL + l] = t[tx][ty + j];
    }
}

// ---------------------------------------------------------------------------
// Launch
// ---------------------------------------------------------------------------
extern "C" void kernel_launch(void* const* d_in, const int* in_sizes, int n_in,
                              void* d_out, int out_size) {
    const float* x    = (const float*)d_in[0];
    const float* W    = (const float*)d_in[1];
    const float* bias = (const float*)d_in[2];
    const int*   idx  = (const int*)d_in[3];
    float*       out  = (float*)d_out;

    cudaFuncSetAttribute(gemm_kernel,
                         cudaFuncAttributeMaxDynamicSharedMemorySize, SMEM_SZ);

    build_xTb_kernel<<<dim3(MM / 32, NN), 256>>>(x);
    gemm_kernel<<<592, 128, SMEM_SZ>>>(W, idx);
    out_transpose_kernel<<<dim3(64, 63), dim3(32, 8)>>>(bias, out);
}